// round 14
// baseline (speedup 1.0000x reference)
#include <cuda_runtime.h>
#include <cuda_bf16.h>
#include <cstddef>
#include <cstdint>

#define BB 4
#define CC 512
#define C8 64
#define NN 4096

// ---------------- scratch (device globals; no runtime allocation) ----------
// Packed bf16x2 (hi/lo) split operands; pair index = k/2, .x = even k.
__device__ unsigned g_xT_hi[(size_t)BB * NN * (CC / 2)];   // [b][n][cpair]
__device__ unsigned g_xT_lo[(size_t)BB * NN * (CC / 2)];
__device__ unsigned g_wv_hi[(size_t)CC * (CC / 2)];        // [co][cpair]
__device__ unsigned g_wv_lo[(size_t)CC * (CC / 2)];
__device__ unsigned g_q_hi[(size_t)BB * NN * (C8 / 2)];    // [b][n][opair]
__device__ unsigned g_q_lo[(size_t)BB * NN * (C8 / 2)];
__device__ unsigned g_k_hi[(size_t)BB * NN * (C8 / 2)];    // [b][n][opair]
__device__ unsigned g_k_lo[(size_t)BB * NN * (C8 / 2)];
__device__ unsigned g_v_hi[(size_t)BB * CC * (NN / 2)];    // [b][c][npair]
__device__ unsigned g_v_lo[(size_t)BB * CC * (NN / 2)];
__device__ unsigned g_P_hi[(size_t)BB * NN * (NN / 2)];    // expS split [b][m][npair]
__device__ unsigned g_P_lo[(size_t)BB * NN * (NN / 2)];
__device__ float    g_rs_part[(size_t)BB * 32 * NN];       // [b][ntile][m] partial rowsums
__device__ float    g_scale[(size_t)BB * NN];              // num_styles / rowsum

// ---------------------------------------------------------------------------
__device__ __forceinline__ unsigned pack_bf16(float a, float b)
{
    __nv_bfloat162 t = __floats2bfloat162_rn(a, b);
    return *reinterpret_cast<unsigned*>(&t);
}

__device__ __forceinline__ void split2(float x0, float x1, unsigned& hi, unsigned& lo)
{
    float h0 = __bfloat162float(__float2bfloat16(x0));
    float h1 = __bfloat162float(__float2bfloat16(x1));
    hi = pack_bf16(h0, h1);
    lo = pack_bf16(x0 - h0, x1 - h1);
}

// Reconstruct one fp32 value from packed hi/lo pair words (half = 0 even, 1 odd)
__device__ __forceinline__ float unsplit_at(const unsigned* __restrict__ hi,
                                            const unsigned* __restrict__ lo,
                                            size_t pairIdx, int half)
{
    unsigned h = hi[pairIdx], l = lo[pairIdx];
    unsigned short hb = half ? (unsigned short)(h >> 16) : (unsigned short)(h & 0xffff);
    unsigned short lb = half ? (unsigned short)(l >> 16) : (unsigned short)(l & 0xffff);
    __nv_bfloat16_raw rh; rh.x = hb;
    __nv_bfloat16_raw rl; rl.x = lb;
    return __bfloat162float(__nv_bfloat16(rh)) + __bfloat162float(__nv_bfloat16(rl));
}

// bf16 mma: D(16x8,f32) += A(16x16,row) * B(16x8,col)
__device__ __forceinline__ void mma_bf16(float d[4], const unsigned a[4],
                                         const unsigned b[2])
{
    asm volatile(
        "mma.sync.aligned.m16n8k16.row.col.f32.bf16.bf16.f32 "
        "{%0,%1,%2,%3}, {%4,%5,%6,%7}, {%8,%9}, {%0,%1,%2,%3};\n"
        : "+f"(d[0]), "+f"(d[1]), "+f"(d[2]), "+f"(d[3])
        : "r"(a[0]), "r"(a[1]), "r"(a[2]), "r"(a[3]),
          "r"(b[0]), "r"(b[1]));
}

// ldmatrix x4: four 8x8 b16 matrices; group-lane i supplies row i's 16B addr.
__device__ __forceinline__ void ldsm_x4(unsigned& r0, unsigned& r1,
                                        unsigned& r2, unsigned& r3, uint32_t a)
{
    asm volatile("ldmatrix.sync.aligned.m8n8.x4.shared.b16 {%0,%1,%2,%3}, [%4];"
                 : "=r"(r0), "=r"(r1), "=r"(r2), "=r"(r3) : "r"(a));
}

__device__ __forceinline__ uint32_t smem_u32(const void* p)
{
    uint32_t a;
    asm("{ .reg .u64 t; cvta.to.shared.u64 t, %1; cvt.u32.u64 %0, t; }"
        : "=r"(a) : "l"(p));
    return a;
}

__device__ __forceinline__ void cp_async16(uint32_t saddr, const void* g)
{
    asm volatile("cp.async.cg.shared.global [%0], [%1], 16;"
                 :: "r"(saddr), "l"(g) : "memory");
}

// ---------------------------------------------------------------------------
// Transpose + split x: x[b][c][n] fp32 -> xT hi/lo [b][n][cpair]
// ---------------------------------------------------------------------------
__global__ __launch_bounds__(256)
void splitT_x(const float* __restrict__ x)
{
    __shared__ float t[32][33];
    const int b  = blockIdx.z;
    const int cB = blockIdx.y * 32;
    const int nB = blockIdx.x * 32;
    const int tid = threadIdx.x;
    const int col = tid & 31, r0 = tid >> 5;

    const float* xb = x + ((size_t)b * CC + cB) * NN + nB;
#pragma unroll
    for (int i = 0; i < 4; i++)
        t[r0 + 8 * i][col] = xb[(size_t)(r0 + 8 * i) * NN + col];
    __syncthreads();

#pragma unroll
    for (int it = 0; it < 2; it++) {
        const int idx = tid + it * 256;     // 32 n x 16 cpair
        const int n  = idx >> 4;
        const int cp = idx & 15;
        unsigned hi, lo;
        split2(t[2 * cp][n], t[2 * cp + 1][n], hi, lo);
        const size_t o = ((size_t)b * NN + nB + n) * (CC / 2) + cB / 2 + cp;
        g_xT_hi[o] = hi;
        g_xT_lo[o] = lo;
    }
}

// ---------------------------------------------------------------------------
// Split Wv: [co][c] fp32 -> hi/lo [co][cpair]
// ---------------------------------------------------------------------------
__global__ __launch_bounds__(256)
void split_w(const float* __restrict__ W)
{
    const int idx = blockIdx.x * 256 + threadIdx.x;   // over CC*CC/2
    const float2 v = *(const float2*)&W[(size_t)idx * 2];
    unsigned hi, lo;
    split2(v.x, v.y, hi, lo);
    g_wv_hi[idx] = hi;
    g_wv_lo[idx] = lo;
}

// ---------------------------------------------------------------------------
// Merged q+k projections (fp32 SIMT, exact):
//   q[b][n][o] = sum_c Wq[o][c] X[b][c][n] + bq[o]   (split -> g_q_*)
//   k[b][n][o] = sum_c Wk[o][c] X[b][c][n] + bk[o]   (split -> g_k_*)
// ---------------------------------------------------------------------------
__global__ __launch_bounds__(256)
void qkproj_kernel(const float* __restrict__ Wq, const float* __restrict__ bq,
                   const float* __restrict__ Wk, const float* __restrict__ bk,
                   const float* __restrict__ X)
{
    __shared__ float Wqs[16][65];  // [c][o]
    __shared__ float Wks[16][65];
    __shared__ float Xs[16][65];   // [c][n]
    __shared__ float stg[64][65];  // [n][o]

    const int b  = blockIdx.z;
    const int nB = blockIdx.x * 64;
    const int tid = threadIdx.x;
    const int tx = tid & 15, ty = tid >> 4;

    const float* Xb = X + (size_t)b * CC * NN;

    float aq[4][4], ak[4][4];
#pragma unroll
    for (int i = 0; i < 4; i++)
#pragma unroll
        for (int j = 0; j < 4; j++) { aq[i][j] = 0.f; ak[i][j] = 0.f; }

    for (int cB = 0; cB < CC; cB += 16) {
        {
            const int o = tid >> 4;
            const int c = tid & 15;
#pragma unroll
            for (int it = 0; it < 4; it++) {
                Wqs[c][o + 16 * it] = Wq[(size_t)(o + 16 * it) * CC + cB + c];
                Wks[c][o + 16 * it] = Wk[(size_t)(o + 16 * it) * CC + cB + c];
            }
        }
        {
            const int r   = tid >> 6;
            const int col = tid & 63;
#pragma unroll
            for (int it = 0; it < 4; it++)
                Xs[r + 4 * it][col] = Xb[(size_t)(cB + r + 4 * it) * NN + nB + col];
        }
        __syncthreads();
#pragma unroll
        for (int kk = 0; kk < 16; kk++) {
            float vq[4], vk[4], bx[4];
#pragma unroll
            for (int i = 0; i < 4; i++) {
                vq[i] = Wqs[kk][ty + 16 * i];
                vk[i] = Wks[kk][ty + 16 * i];
            }
#pragma unroll
            for (int j = 0; j < 4; j++) bx[j] = Xs[kk][tx + 16 * j];
#pragma unroll
            for (int i = 0; i < 4; i++)
#pragma unroll
                for (int j = 0; j < 4; j++) {
                    aq[i][j] += vq[i] * bx[j];
                    ak[i][j] += vk[i] * bx[j];
                }
        }
        __syncthreads();
    }

    // q: stage [n][o], split-write
#pragma unroll
    for (int i = 0; i < 4; i++) {
        const float bo = bq[ty + 16 * i];
#pragma unroll
        for (int j = 0; j < 4; j++)
            stg[tx + 16 * j][ty + 16 * i] = aq[i][j] + bo;
    }
    __syncthreads();
#pragma unroll
    for (int it = 0; it < 8; it++) {
        const int idx = tid + it * 256;
        const int n = idx >> 5, op = idx & 31;
        unsigned hi, lo;
        split2(stg[n][2 * op], stg[n][2 * op + 1], hi, lo);
        const size_t o = ((size_t)b * NN + nB + n) * (C8 / 2) + op;
        g_q_hi[o] = hi;
        g_q_lo[o] = lo;
    }
    __syncthreads();

    // k: stage, split-write
#pragma unroll
    for (int i = 0; i < 4; i++) {
        const float bo = bk[ty + 16 * i];
#pragma unroll
        for (int j = 0; j < 4; j++)
            stg[tx + 16 * j][ty + 16 * i] = ak[i][j] + bo;
    }
    __syncthreads();
#pragma unroll
    for (int it = 0; it < 8; it++) {
        const int idx = tid + it * 256;
        const int n = idx >> 5, op = idx & 31;
        unsigned hi, lo;
        split2(stg[n][2 * op], stg[n][2 * op + 1], hi, lo);
        const size_t o = ((size_t)b * NN + nB + n) * (C8 / 2) + op;
        g_k_hi[o] = hi;
        g_k_lo[o] = lo;
    }
}

// ---------------------------------------------------------------------------
// bf16x3 mainloop, cp.async 2-stage pipeline + ldmatrix, ONE barrier/K-tile.
// 128x128 tile, KT=32 (16 pairs), 8 warps (2 M x 4 N), warp tile 64x32.
// Stage layout: [Ah | Al | Bh | Bl], each 128 rows x SMS(20) words.
// Loop order per tile: wait_group 0 -> syncthreads -> ISSUE(kt+1) -> MMA(kt).
// Hazards: s^1's last readers (iter kt-1 MMA) are ordered before ISSUE by the
// barrier; stage-s data (issued iter kt-1) is drained by wait_group and
// published by the same barrier. Prefetch distance = one full MMA phase.
// ---------------------------------------------------------------------------
#define SMS 20
#define ARR_B  (128 * SMS * 4)      // 10240 bytes per array
#define STG_B  (4 * ARR_B)          // 40960 bytes per stage
#define PIPE_B (2 * STG_B)          // 81920 bytes total

template <int LDA, int LDB, int NKT>
__device__ __forceinline__ void bf16x3_mainloop_ca(
    const unsigned* __restrict__ Ahi, const unsigned* __restrict__ Alo,
    const unsigned* __restrict__ Bhi, const unsigned* __restrict__ Blo,
    uint32_t sbase, float acc[4][4][4])
{
    const int tid  = threadIdx.x;
    const int lane = tid & 31, warp = tid >> 5;
    const int wm = (warp & 1) * 64;
    const int wn = (warp >> 1) * 32;
    const int row = tid >> 2;          // 0..63
    const int kp  = (tid & 3) * 4;     // 0,4,8,12

    const uint32_t d0 = (uint32_t)((row * SMS + kp) * 4);
    const uint32_t d1 = (uint32_t)(((row + 64) * SMS + kp) * 4);

    // ldmatrix lane-address components
    const int rA  = ((lane >> 3) & 1) * 8 + (lane & 7);  // A: m0/m1 row pairs
    const int kwA = (lane >> 4) * 4;                     // A: m2/m3 k-half
    const int rB  = (lane >> 4) * 8 + (lane & 7);        // B: nt row pairs
    const int kwB = ((lane >> 3) & 1) * 4;               // B: k-half

#define ISSUE(kt, s)                                                          \
    do {                                                                      \
        const size_t off = (size_t)(kt) * 16 + kp;                            \
        const uint32_t sb = sbase + (s) * STG_B;                              \
        cp_async16(sb + d0,             Ahi + (size_t)row * LDA + off);       \
        cp_async16(sb + d1,             Ahi + (size_t)(row + 64) * LDA + off);\
        cp_async16(sb + ARR_B + d0,     Alo + (size_t)row * LDA + off);       \
        cp_async16(sb + ARR_B + d1,     Alo + (size_t)(row + 64) * LDA + off);\
        cp_async16(sb + 2 * ARR_B + d0, Bhi + (size_t)row * LDB + off);       \
        cp_async16(sb + 2 * ARR_B + d1, Bhi + (size_t)(row + 64) * LDB + off);\
        cp_async16(sb + 3 * ARR_B + d0, Blo + (size_t)row * LDB + off);       \
        cp_async16(sb + 3 * ARR_B + d1, Blo + (size_t)(row + 64) * LDB + off);\
        asm volatile("cp.async.commit_group;" ::: "memory");                  \
    } while (0)

    ISSUE(0, 0);

    for (int kt = 0; kt < NKT; kt++) {
        const int s = kt & 1;

        asm volatile("cp.async.wait_group 0;" ::: "memory");
        __syncthreads();
        if (kt + 1 < NKT) ISSUE(kt + 1, s ^ 1);

        const uint32_t sAh = sbase + s * STG_B;
        const uint32_t sAl = sAh + ARR_B;
        const uint32_t sBh = sAh + 2 * ARR_B;
        const uint32_t sBl = sAh + 3 * ARR_B;

#pragma unroll
        for (int ks = 0; ks < 2; ks++) {
            unsigned bh[4][2], bl[4][2];
#pragma unroll
            for (int j = 0; j < 2; j++) {
                const uint32_t boff =
                    (uint32_t)(((wn + 16 * j + rB) * SMS + ks * 8 + kwB) << 2);
                ldsm_x4(bh[2 * j][0], bh[2 * j][1], bh[2 * j + 1][0],
                        bh[2 * j + 1][1], sBh + boff);
                ldsm_x4(bl[2 * j][0], bl[2 * j][1], bl[2 * j + 1][0],
                        bl[2 * j + 1][1], sBl + boff);
            }
#pragma unroll
            for (int mt = 0; mt < 4; mt++) {
                const uint32_t aoff =
                    (uint32_t)(((wm + mt * 16 + rA) * SMS + ks * 8 + kwA) << 2);
                unsigned ah[4], al[4];
                ldsm_x4(ah[0], ah[1], ah[2], ah[3], sAh + aoff);
                ldsm_x4(al[0], al[1], al[2], al[3], sAl + aoff);
#pragma unroll
                for (int nt = 0; nt < 4; nt++) {
                    mma_bf16(acc[mt][nt], ah, bh[nt]);
                    mma_bf16(acc[mt][nt], ah, bl[nt]);
                    mma_bf16(acc[mt][nt], al, bh[nt]);
                }
            }
        }
    }
#undef ISSUE
}

// ---------------------------------------------------------------------------
// v projection: g_v split[b][co][n] = sum_c Wv[co][c] x[b][c][n] + bv[co]
// ---------------------------------------------------------------------------
__global__ __launch_bounds__(256, 2)
void vproj_bf16(const float* __restrict__ bias)
{
    extern __shared__ char smem[];
    const uint32_t sbase = smem_u32(smem);

    const int b   = blockIdx.z;
    const int coB = blockIdx.y * 128;
    const int nB  = blockIdx.x * 128;

    float acc[4][4][4];
#pragma unroll
    for (int mt = 0; mt < 4; mt++)
#pragma unroll
        for (int nt = 0; nt < 4; nt++)
#pragma unroll
            for (int r = 0; r < 4; r++) acc[mt][nt][r] = 0.f;

    bf16x3_mainloop_ca<CC / 2, CC / 2, CC / 32>(
        g_wv_hi + (size_t)coB * (CC / 2), g_wv_lo + (size_t)coB * (CC / 2),
        g_xT_hi + ((size_t)b * NN + nB) * (CC / 2),
        g_xT_lo + ((size_t)b * NN + nB) * (CC / 2),
        sbase, acc);

    const int lane = threadIdx.x & 31, warp = threadIdx.x >> 5;
    const int g = lane >> 2, tq = lane & 3;
    const int wm = (warp & 1) * 64, wn = (warp >> 1) * 32;

#pragma unroll
    for (int mt = 0; mt < 4; mt++)
#pragma unroll
        for (int half = 0; half < 2; half++) {
            const int c = coB + wm + mt * 16 + g + half * 8;
            const float bo = bias[c];
            const size_t rowoff = ((size_t)b * CC + c) * (NN / 2);
#pragma unroll
            for (int nt = 0; nt < 4; nt++) {
                unsigned hi, lo;
                split2(acc[mt][nt][half * 2 + 0] + bo,
                       acc[mt][nt][half * 2 + 1] + bo, hi, lo);
                const size_t o = rowoff + (nB + wn + nt * 8) / 2 + tq;
                g_v_hi[o] = hi;
                g_v_lo[o] = lo;
            }
        }
}

// ---------------------------------------------------------------------------
// Logits + exp: expS[b][m][n] = exp(sum_o q[m][o] k[n][o]).
// Writes expS as bf16 hi/lo split pairs + deterministic per-(m, n-tile)
// partial rowsums staged through smem (no atomics -> replay-deterministic).
// ---------------------------------------------------------------------------
__global__ __launch_bounds__(256, 2)
void logits_exp_bf16()
{
    extern __shared__ char smem[];
    const uint32_t sbase = smem_u32(smem);

    const int b  = blockIdx.z;
    const int mB = blockIdx.y * 128;
    const int nB = blockIdx.x * 128;
    const int tid = threadIdx.x;

    float acc[4][4][4];
#pragma unroll
    for (int mt = 0; mt < 4; mt++)
#pragma unroll
        for (int nt = 0; nt < 4; nt++)
#pragma unroll
            for (int r = 0; r < 4; r++) acc[mt][nt][r] = 0.f;

    bf16x3_mainloop_ca<C8 / 2, C8 / 2, C8 / 32>(
        g_q_hi + ((size_t)b * NN + mB) * (C8 / 2),
        g_q_lo + ((size_t)b * NN + mB) * (C8 / 2),
        g_k_hi + ((size_t)b * NN + nB) * (C8 / 2),
        g_k_lo + ((size_t)b * NN + nB) * (C8 / 2),
        sbase, acc);

    // mainloop no longer ends with a barrier; order MMA reads before smem reuse
    __syncthreads();

    const int lane = tid & 31, warp = tid >> 5;
    const int g = lane >> 2, tq = lane & 3;
    const int wm = (warp & 1) * 64, wn = (warp >> 1) * 32;
    const int slot = (warp >> 1) * 4 + tq;     // 0..15, unique per (ml)

    float* rps = (float*)smem;                 // [128][16]

#pragma unroll
    for (int mt = 0; mt < 4; mt++)
#pragma unroll
        for (int half = 0; half < 2; half++) {
            const int ml = wm + mt * 16 + g + half * 8;
            const size_t prow = ((size_t)b * NN + mB + ml) * (NN / 2);
            float rsum = 0.f;
#pragma unroll
            for (int nt = 0; nt < 4; nt++) {
                float e0 = __expf(acc[mt][nt][half * 2 + 0]);
                float e1 = __expf(acc[mt][nt][half * 2 + 1]);
                unsigned hi, lo;
                split2(e0, e1, hi, lo);
                const size_t pidx = prow + (nB + wn + nt * 8) / 2 + tq;
                g_P_hi[pidx] = hi;
                g_P_lo[pidx] = lo;
                rsum += e0 + e1;
            }
            rps[ml * 16 + slot] = rsum;
        }
    __syncthreads();

    if (tid < 128) {
        float s = 0.f;
#pragma unroll
        for (int i = 0; i < 16; i++) s += rps[tid * 16 + i];
        g_rs_part[((size_t)b * 32 + (nB >> 7)) * NN + mB + tid] = s;
    }
}

// ---------------------------------------------------------------------------
// Reduce partial rowsums -> per-row scale = num_styles / rowsum
// ---------------------------------------------------------------------------
__global__ __launch_bounds__(256)
void reduce_scale(const int* __restrict__ num_styles)
{
    const int idx = blockIdx.x * 256 + threadIdx.x;   // BB*NN total
    const int b = idx >> 12;
    const int m = idx & (NN - 1);
    float s = 0.f;
#pragma unroll
    for (int t = 0; t < 32; t++)
        s += g_rs_part[((size_t)b * 32 + t) * NN + m];
    g_scale[(size_t)b * NN + m] = (float)num_styles[0] / s;
}

// ---------------------------------------------------------------------------
// Heavy GEMM: out[b][c][m] = gamma*(sum_n v[c][n] expS[m][n])*scale[m]
//                           - gamma*[m==0]*corr*v[c][sidx] + x[b][c][m]
// where corr = expS[0][sidx]*scale[0] (the zeroed style entry).
// c-tiles fastest in grid.x so blocks sharing a P slice co-run (L2 reuse).
// ---------------------------------------------------------------------------
__global__ __launch_bounds__(256, 2)
void out_gemm_bf16(const float* __restrict__ x, const float* __restrict__ gamma,
                   const int* __restrict__ style_idx, float* __restrict__ out)
{
    extern __shared__ char smem[];
    const uint32_t sbase = smem_u32(smem);

    const int b  = blockIdx.z;
    const int cB = blockIdx.x * 128;
    const int mB = blockIdx.y * 128;

    float acc[4][4][4];
#pragma unroll
    for (int mt = 0; mt < 4; mt++)
#pragma unroll
        for (int nt = 0; nt < 4; nt++)
#pragma unroll
            for (int r = 0; r < 4; r++) acc[mt][nt][r] = 0.f;

    bf16x3_mainloop_ca<NN / 2, NN / 2, NN / 32>(
        g_v_hi + ((size_t)b * CC + cB) * (NN / 2),
        g_v_lo + ((size_t)b * CC + cB) * (NN / 2),
        g_P_hi + ((size_t)b * NN + mB) * (NN / 2),
        g_P_lo + ((size_t)b * NN + mB) * (NN / 2),
        sbase, acc);

    const int lane = threadIdx.x & 31, warp = threadIdx.x >> 5;
    const int g = lane >> 2, tq = lane & 3;
    const int wm = (warp & 1) * 64, wn = (warp >> 1) * 32;

    const float gm = gamma[0];

    // per-column softmax scales (8 columns per thread)
    float sc[4][2];
#pragma unroll
    for (int nt = 0; nt < 4; nt++) {
        const int m = mB + wn + nt * 8 + 2 * tq;
        sc[nt][0] = g_scale[(size_t)b * NN + m];
        sc[nt][1] = g_scale[(size_t)b * NN + m + 1];
    }

    // style-zero correction setup (only threads owning column m == 0)
    const bool fix0 = (mB == 0) && (wn == 0) && (tq == 0);
    float corr = 0.f;
    int sx = 0;
    if (fix0) {
        sx = style_idx[b];
        const float e0 = unsplit_at(g_P_hi, g_P_lo,
                                    ((size_t)b * NN + 0) * (NN / 2) + (sx >> 1),
                                    sx & 1);
        corr = e0 * g_scale[(size_t)b * NN + 0];
    }

#pragma unroll
    for (int mt = 0; mt < 4; mt++)
#pragma unroll
        for (int half = 0; half < 2; half++) {
            const int c = cB + wm + mt * 16 + g + half * 8;
            const float* xr   = x   + ((size_t)b * CC + c) * NN;
            float*       orow = out + ((size_t)b * CC + c) * NN;
#pragma unroll
            for (int nt = 0; nt < 4; nt++) {
                const int m = mB + wn + nt * 8 + 2 * tq;
                float a0 = acc[mt][nt][half * 2 + 0] * sc[nt][0];
                float a1 = acc[mt][nt][half * 2 + 1] * sc[nt][1];
                if (nt == 0 && fix0) {
                    const float vc = unsplit_at(
                        g_v_hi, g_v_lo,
                        ((size_t)b * CC + c) * (NN / 2) + (sx >> 1), sx & 1);
                    a0 -= corr * vc;           // m == 0 column
                }
                float2 r;
                r.x = gm * a0 + xr[m];
                r.y = gm * a1 + xr[m + 1];
                *(float2*)&orow[m] = r;
            }
        }
}

// ---------------------------------------------------------------------------
extern "C" void kernel_launch(void* const* d_in, const int* in_sizes, int n_in,
                              void* d_out, int out_size)
{
    const float* x     = (const float*)d_in[0];
    const float* Wq    = (const float*)d_in[1];
    const float* bq    = (const float*)d_in[2];
    const float* Wk    = (const float*)d_in[3];
    const float* bk    = (const float*)d_in[4];
    const float* Wv    = (const float*)d_in[5];
    const float* bv    = (const float*)d_in[6];
    const float* gamma = (const float*)d_in[7];
    const int*   sidx  = (const int*)d_in[8];
    const int*   nsty  = (const int*)d_in[9];
    float* out = (float*)d_out;

    cudaFuncSetAttribute(vproj_bf16,
                         cudaFuncAttributeMaxDynamicSharedMemorySize, PIPE_B);
    cudaFuncSetAttribute(logits_exp_bf16,
                         cudaFuncAttributeMaxDynamicSharedMemorySize, PIPE_B);
    cudaFuncSetAttribute(out_gemm_bf16,
                         cudaFuncAttributeMaxDynamicSharedMemorySize, PIPE_B);

    // Prep: transpose+split x, split Wv
    splitT_x<<<dim3(NN / 32, CC / 32, BB), 256>>>(x);
    split_w<<<(CC * (CC / 2)) / 256, 256>>>(Wv);

    // merged q+k projections (fp32 exact), written split [n][o]
    qkproj_kernel<<<dim3(NN / 64, 1, BB), 256>>>(Wq, bq, Wk, bk, x);

    // v projection (bf16x3, cp.async + ldmatrix, 1 barrier/tile) -> split V
    vproj_bf16<<<dim3(NN / 128, CC / 128, BB), 256, PIPE_B>>>(bv);

    // logits + exp -> split expS + partial rowsums
    logits_exp_bf16<<<dim3(NN / 128, NN / 128, BB), 256, PIPE_B>>>();

    // rowsum reduce -> per-row scale
    reduce_scale<<<(BB * NN) / 256, 256>>>(nsty);

    // out = gamma * (V @ expS^T) * scale + correction + x
    out_gemm_bf16<<<dim3(CC / 128, NN / 128, BB), 256, PIPE_B>>>(x, gamma, sidx, out);
}

// round 17
// speedup vs baseline: 1.1388x; 1.1388x over previous
#include <cuda_runtime.h>
#include <cuda_bf16.h>
#include <cstddef>
#include <cstdint>

#define BB 4
#define CC 512
#define C8 64
#define NN 4096

// ---------------- scratch (device globals; no runtime allocation) ----------
// Packed bf16x2 (hi/lo) split operands; pair index = k/2, .x = even k.
__device__ unsigned g_xT_hi[(size_t)BB * NN * (CC / 2)];   // [b][n][cpair]
__device__ unsigned g_xT_lo[(size_t)BB * NN * (CC / 2)];
__device__ unsigned g_wv_hi[(size_t)CC * (CC / 2)];        // [co][cpair]
__device__ unsigned g_wv_lo[(size_t)CC * (CC / 2)];
__device__ unsigned g_q_hi[(size_t)BB * NN * (C8 / 2)];    // [b][n][opair]
__device__ unsigned g_q_lo[(size_t)BB * NN * (C8 / 2)];
__device__ unsigned g_k_hi[(size_t)BB * NN * (C8 / 2)];    // [b][n][opair]
__device__ unsigned g_k_lo[(size_t)BB * NN * (C8 / 2)];
__device__ unsigned g_v_hi[(size_t)BB * CC * (NN / 2)];    // [b][c][npair]
__device__ unsigned g_v_lo[(size_t)BB * CC * (NN / 2)];
__device__ unsigned g_P_hi[(size_t)BB * NN * (NN / 2)];    // expS split [b][m][npair]
__device__ unsigned g_P_lo[(size_t)BB * NN * (NN / 2)];
__device__ float    g_rs_part[(size_t)BB * 32 * NN];       // [b][ntile][m] partial rowsums
__device__ float    g_scale[(size_t)BB * NN];              // num_styles / rowsum

// ---------------------------------------------------------------------------
__device__ __forceinline__ unsigned pack_bf16(float a, float b)
{
    __nv_bfloat162 t = __floats2bfloat162_rn(a, b);
    return *reinterpret_cast<unsigned*>(&t);
}

__device__ __forceinline__ void split2(float x0, float x1, unsigned& hi, unsigned& lo)
{
    float h0 = __bfloat162float(__float2bfloat16(x0));
    float h1 = __bfloat162float(__float2bfloat16(x1));
    hi = pack_bf16(h0, h1);
    lo = pack_bf16(x0 - h0, x1 - h1);
}

// Reconstruct one fp32 value from packed hi/lo pair words (half = 0 even, 1 odd)
__device__ __forceinline__ float unsplit_at(const unsigned* __restrict__ hi,
                                            const unsigned* __restrict__ lo,
                                            size_t pairIdx, int half)
{
    unsigned h = hi[pairIdx], l = lo[pairIdx];
    unsigned short hb = half ? (unsigned short)(h >> 16) : (unsigned short)(h & 0xffff);
    unsigned short lb = half ? (unsigned short)(l >> 16) : (unsigned short)(l & 0xffff);
    __nv_bfloat16_raw rh; rh.x = hb;
    __nv_bfloat16_raw rl; rl.x = lb;
    return __bfloat162float(__nv_bfloat16(rh)) + __bfloat162float(__nv_bfloat16(rl));
}

// bf16 mma: D(16x8,f32) += A(16x16,row) * B(16x8,col)
__device__ __forceinline__ void mma_bf16(float d[4], const unsigned a[4],
                                         const unsigned b[2])
{
    asm volatile(
        "mma.sync.aligned.m16n8k16.row.col.f32.bf16.bf16.f32 "
        "{%0,%1,%2,%3}, {%4,%5,%6,%7}, {%8,%9}, {%0,%1,%2,%3};\n"
        : "+f"(d[0]), "+f"(d[1]), "+f"(d[2]), "+f"(d[3])
        : "r"(a[0]), "r"(a[1]), "r"(a[2]), "r"(a[3]),
          "r"(b[0]), "r"(b[1]));
}

// ldmatrix x4: four 8x8 b16 matrices; group-lane i supplies row i's 16B addr.
__device__ __forceinline__ void ldsm_x4(unsigned& r0, unsigned& r1,
                                        unsigned& r2, unsigned& r3, uint32_t a)
{
    asm volatile("ldmatrix.sync.aligned.m8n8.x4.shared.b16 {%0,%1,%2,%3}, [%4];"
                 : "=r"(r0), "=r"(r1), "=r"(r2), "=r"(r3) : "r"(a));
}

__device__ __forceinline__ uint32_t smem_u32(const void* p)
{
    uint32_t a;
    asm("{ .reg .u64 t; cvta.to.shared.u64 t, %1; cvt.u32.u64 %0, t; }"
        : "=r"(a) : "l"(p));
    return a;
}

__device__ __forceinline__ void cp_async16(uint32_t saddr, const void* g)
{
    asm volatile("cp.async.cg.shared.global [%0], [%1], 16;"
                 :: "r"(saddr), "l"(g) : "memory");
}

// ---------------------------------------------------------------------------
// Transpose + split x: x[b][c][n] fp32 -> xT hi/lo [b][n][cpair]
// ---------------------------------------------------------------------------
__global__ __launch_bounds__(256)
void splitT_x(const float* __restrict__ x)
{
    __shared__ float t[32][33];
    const int b  = blockIdx.z;
    const int cB = blockIdx.y * 32;
    const int nB = blockIdx.x * 32;
    const int tid = threadIdx.x;
    const int col = tid & 31, r0 = tid >> 5;

    const float* xb = x + ((size_t)b * CC + cB) * NN + nB;
#pragma unroll
    for (int i = 0; i < 4; i++)
        t[r0 + 8 * i][col] = xb[(size_t)(r0 + 8 * i) * NN + col];
    __syncthreads();

#pragma unroll
    for (int it = 0; it < 2; it++) {
        const int idx = tid + it * 256;     // 32 n x 16 cpair
        const int n  = idx >> 4;
        const int cp = idx & 15;
        unsigned hi, lo;
        split2(t[2 * cp][n], t[2 * cp + 1][n], hi, lo);
        const size_t o = ((size_t)b * NN + nB + n) * (CC / 2) + cB / 2 + cp;
        g_xT_hi[o] = hi;
        g_xT_lo[o] = lo;
    }
}

// ---------------------------------------------------------------------------
// Split Wv: [co][c] fp32 -> hi/lo [co][cpair]
// ---------------------------------------------------------------------------
__global__ __launch_bounds__(256)
void split_w(const float* __restrict__ W)
{
    const int idx = blockIdx.x * 256 + threadIdx.x;   // over CC*CC/2
    const float2 v = *(const float2*)&W[(size_t)idx * 2];
    unsigned hi, lo;
    split2(v.x, v.y, hi, lo);
    g_wv_hi[idx] = hi;
    g_wv_lo[idx] = lo;
}

// ---------------------------------------------------------------------------
// Merged q+k projections (fp32 SIMT, exact):
//   q[b][n][o] = sum_c Wq[o][c] X[b][c][n] + bq[o]   (split -> g_q_*)
//   k[b][n][o] = sum_c Wk[o][c] X[b][c][n] + bk[o]   (split -> g_k_*)
// ---------------------------------------------------------------------------
__global__ __launch_bounds__(256)
void qkproj_kernel(const float* __restrict__ Wq, const float* __restrict__ bq,
                   const float* __restrict__ Wk, const float* __restrict__ bk,
                   const float* __restrict__ X)
{
    __shared__ float Wqs[16][65];  // [c][o]
    __shared__ float Wks[16][65];
    __shared__ float Xs[16][65];   // [c][n]
    __shared__ float stg[64][65];  // [n][o]

    const int b  = blockIdx.z;
    const int nB = blockIdx.x * 64;
    const int tid = threadIdx.x;
    const int tx = tid & 15, ty = tid >> 4;

    const float* Xb = X + (size_t)b * CC * NN;

    float aq[4][4], ak[4][4];
#pragma unroll
    for (int i = 0; i < 4; i++)
#pragma unroll
        for (int j = 0; j < 4; j++) { aq[i][j] = 0.f; ak[i][j] = 0.f; }

    for (int cB = 0; cB < CC; cB += 16) {
        {
            const int o = tid >> 4;
            const int c = tid & 15;
#pragma unroll
            for (int it = 0; it < 4; it++) {
                Wqs[c][o + 16 * it] = Wq[(size_t)(o + 16 * it) * CC + cB + c];
                Wks[c][o + 16 * it] = Wk[(size_t)(o + 16 * it) * CC + cB + c];
            }
        }
        {
            const int r   = tid >> 6;
            const int col = tid & 63;
#pragma unroll
            for (int it = 0; it < 4; it++)
                Xs[r + 4 * it][col] = Xb[(size_t)(cB + r + 4 * it) * NN + nB + col];
        }
        __syncthreads();
#pragma unroll
        for (int kk = 0; kk < 16; kk++) {
            float vq[4], vk[4], bx[4];
#pragma unroll
            for (int i = 0; i < 4; i++) {
                vq[i] = Wqs[kk][ty + 16 * i];
                vk[i] = Wks[kk][ty + 16 * i];
            }
#pragma unroll
            for (int j = 0; j < 4; j++) bx[j] = Xs[kk][tx + 16 * j];
#pragma unroll
            for (int i = 0; i < 4; i++)
#pragma unroll
                for (int j = 0; j < 4; j++) {
                    aq[i][j] += vq[i] * bx[j];
                    ak[i][j] += vk[i] * bx[j];
                }
        }
        __syncthreads();
    }

    // q: stage [n][o], split-write
#pragma unroll
    for (int i = 0; i < 4; i++) {
        const float bo = bq[ty + 16 * i];
#pragma unroll
        for (int j = 0; j < 4; j++)
            stg[tx + 16 * j][ty + 16 * i] = aq[i][j] + bo;
    }
    __syncthreads();
#pragma unroll
    for (int it = 0; it < 8; it++) {
        const int idx = tid + it * 256;
        const int n = idx >> 5, op = idx & 31;
        unsigned hi, lo;
        split2(stg[n][2 * op], stg[n][2 * op + 1], hi, lo);
        const size_t o = ((size_t)b * NN + nB + n) * (C8 / 2) + op;
        g_q_hi[o] = hi;
        g_q_lo[o] = lo;
    }
    __syncthreads();

    // k: stage, split-write
#pragma unroll
    for (int i = 0; i < 4; i++) {
        const float bo = bk[ty + 16 * i];
#pragma unroll
        for (int j = 0; j < 4; j++)
            stg[tx + 16 * j][ty + 16 * i] = ak[i][j] + bo;
    }
    __syncthreads();
#pragma unroll
    for (int it = 0; it < 8; it++) {
        const int idx = tid + it * 256;
        const int n = idx >> 5, op = idx & 31;
        unsigned hi, lo;
        split2(stg[n][2 * op], stg[n][2 * op + 1], hi, lo);
        const size_t o = ((size_t)b * NN + nB + n) * (C8 / 2) + op;
        g_k_hi[o] = hi;
        g_k_lo[o] = lo;
    }
}

// ---------------------------------------------------------------------------
// bf16x3 mainloop, cp.async THREE-stage pipeline + ldmatrix, XOR-swizzled.
// 128x128 tile, KT=32 (16 pairs), 8 warps (2 M x 4 N), warp tile 64x32.
// Stage layout: [Ah | Al | Bh | Bl], each 128 rows x 64B (SMS=16 words).
// Swizzle: 16B slot index s -> s ^ ((row>>1)&3). Row stride 64B keeps every
// cp.async 16B-aligned; swizzle makes both the write phases and all ldmatrix
// phases hit 8 distinct bank groups (proof: group=(4*row+s_sw) mod 8).
// Since warp row bases are multiples of 16, the XOR term is a per-thread
// constant. Per tile: wait_group(1|0) -> barrier -> ISSUE(kt+2) -> MMA(kt).
// MMA order term-major: dependent same-acc MMAs 4 apart.
// ---------------------------------------------------------------------------
#define SMS 16
#define ARR_B  (128 * SMS * 4)      // 8192 bytes per array
#define STG_B  (4 * ARR_B)          // 32768 bytes per stage
#define NSTAGE 3
#define PIPE_B (NSTAGE * STG_B)     // 98304 bytes total

template <int LDA, int LDB, int NKT>
__device__ __forceinline__ void bf16x3_mainloop_ca(
    const unsigned* __restrict__ Ahi, const unsigned* __restrict__ Alo,
    const unsigned* __restrict__ Bhi, const unsigned* __restrict__ Blo,
    uint32_t sbase, float acc[4][4][4])
{
    const int tid  = threadIdx.x;
    const int lane = tid & 31, warp = tid >> 5;
    const int wm = (warp & 1) * 64;
    const int wn = (warp >> 1) * 32;
    const int row = tid >> 2;          // 0..63
    const int slot = tid & 3;          // 16B slot 0..3
    const int kp  = slot * 4;          // word offset in gmem row

    // swizzled write offsets (row and row+64 share (row>>1)&3)
    const int swW = (row >> 1) & 3;
    const uint32_t d0 = (uint32_t)(row * 64 + ((slot ^ swW) * 16));
    const uint32_t d1 = d0 + 64 * 64;

    // ldmatrix lane-address components
    const int rA  = ((lane >> 3) & 1) * 8 + (lane & 7);  // A: m0/m1 row pairs
    const int kA  = (lane >> 4);                         // A: k-half slot bit
    const int rB  = (lane >> 4) * 8 + (lane & 7);        // B: nt row pairs
    const int kB  = (lane >> 3) & 1;                     // B: k-half slot bit
    const int swA = (rA >> 1) & 3;                       // per-thread swizzle
    const int swB = (rB >> 1) & 3;

#define ISSUE(kt, s)                                                          \
    do {                                                                      \
        const size_t off = (size_t)(kt) * 16 + kp;                            \
        const uint32_t sb = sbase + (s) * STG_B;                              \
        cp_async16(sb + d0,             Ahi + (size_t)row * LDA + off);       \
        cp_async16(sb + d1,             Ahi + (size_t)(row + 64) * LDA + off);\
        cp_async16(sb + ARR_B + d0,     Alo + (size_t)row * LDA + off);       \
        cp_async16(sb + ARR_B + d1,     Alo + (size_t)(row + 64) * LDA + off);\
        cp_async16(sb + 2 * ARR_B + d0, Bhi + (size_t)row * LDB + off);       \
        cp_async16(sb + 2 * ARR_B + d1, Bhi + (size_t)(row + 64) * LDB + off);\
        cp_async16(sb + 3 * ARR_B + d0, Blo + (size_t)row * LDB + off);       \
        cp_async16(sb + 3 * ARR_B + d1, Blo + (size_t)(row + 64) * LDB + off);\
        asm volatile("cp.async.commit_group;" ::: "memory");                  \
    } while (0)

    ISSUE(0, 0);
    if (NKT > 1) ISSUE(1, 1);

    int s = 0;
    for (int kt = 0; kt < NKT; kt++) {
        if (kt < NKT - 1)
            asm volatile("cp.async.wait_group 1;" ::: "memory");
        else
            asm volatile("cp.async.wait_group 0;" ::: "memory");
        __syncthreads();

        if (kt + 2 < NKT) {
            const int s2 = (s + 2 >= NSTAGE) ? s + 2 - NSTAGE : s + 2;
            ISSUE(kt + 2, s2);
        }

        const uint32_t sAh = sbase + s * STG_B;
        const uint32_t sAl = sAh + ARR_B;
        const uint32_t sBh = sAh + 2 * ARR_B;
        const uint32_t sBl = sAh + 3 * ARR_B;

#pragma unroll
        for (int ks = 0; ks < 2; ks++) {
            unsigned bh[4][2], bl[4][2];
#pragma unroll
            for (int j = 0; j < 2; j++) {
                const uint32_t boff =
                    (uint32_t)((wn + 16 * j + rB) * 64 +
                               (((ks * 2 + kB) ^ swB) * 16));
                ldsm_x4(bh[2 * j][0], bh[2 * j][1], bh[2 * j + 1][0],
                        bh[2 * j + 1][1], sBh + boff);
                ldsm_x4(bl[2 * j][0], bl[2 * j][1], bl[2 * j + 1][0],
                        bl[2 * j + 1][1], sBl + boff);
            }
#pragma unroll
            for (int mt = 0; mt < 4; mt++) {
                const uint32_t aoff =
                    (uint32_t)((wm + mt * 16 + rA) * 64 +
                               (((ks * 2 + kA) ^ swA) * 16));
                unsigned ah[4], al[4];
                ldsm_x4(ah[0], ah[1], ah[2], ah[3], sAh + aoff);
                ldsm_x4(al[0], al[1], al[2], al[3], sAl + aoff);
                // term-major: dependent same-acc MMAs are 4 apart
#pragma unroll
                for (int nt = 0; nt < 4; nt++)
                    mma_bf16(acc[mt][nt], ah, bh[nt]);
#pragma unroll
                for (int nt = 0; nt < 4; nt++)
                    mma_bf16(acc[mt][nt], ah, bl[nt]);
#pragma unroll
                for (int nt = 0; nt < 4; nt++)
                    mma_bf16(acc[mt][nt], al, bh[nt]);
            }
        }
        s = (s + 1 == NSTAGE) ? 0 : s + 1;
    }
#undef ISSUE
}

// ---------------------------------------------------------------------------
// v projection: g_v split[b][co][n] = sum_c Wv[co][c] x[b][c][n] + bv[co]
// ---------------------------------------------------------------------------
__global__ __launch_bounds__(256, 2)
void vproj_bf16(const float* __restrict__ bias)
{
    extern __shared__ char smem[];
    const uint32_t sbase = smem_u32(smem);

    const int b   = blockIdx.z;
    const int coB = blockIdx.y * 128;
    const int nB  = blockIdx.x * 128;

    float acc[4][4][4];
#pragma unroll
    for (int mt = 0; mt < 4; mt++)
#pragma unroll
        for (int nt = 0; nt < 4; nt++)
#pragma unroll
            for (int r = 0; r < 4; r++) acc[mt][nt][r] = 0.f;

    bf16x3_mainloop_ca<CC / 2, CC / 2, CC / 32>(
        g_wv_hi + (size_t)coB * (CC / 2), g_wv_lo + (size_t)coB * (CC / 2),
        g_xT_hi + ((size_t)b * NN + nB) * (CC / 2),
        g_xT_lo + ((size_t)b * NN + nB) * (CC / 2),
        sbase, acc);

    const int lane = threadIdx.x & 31, warp = threadIdx.x >> 5;
    const int g = lane >> 2, tq = lane & 3;
    const int wm = (warp & 1) * 64, wn = (warp >> 1) * 32;

#pragma unroll
    for (int mt = 0; mt < 4; mt++)
#pragma unroll
        for (int half = 0; half < 2; half++) {
            const int c = coB + wm + mt * 16 + g + half * 8;
            const float bo = bias[c];
            const size_t rowoff = ((size_t)b * CC + c) * (NN / 2);
#pragma unroll
            for (int nt = 0; nt < 4; nt++) {
                unsigned hi, lo;
                split2(acc[mt][nt][half * 2 + 0] + bo,
                       acc[mt][nt][half * 2 + 1] + bo, hi, lo);
                const size_t o = rowoff + (nB + wn + nt * 8) / 2 + tq;
                g_v_hi[o] = hi;
                g_v_lo[o] = lo;
            }
        }
}

// ---------------------------------------------------------------------------
// Logits + exp: expS[b][m][n] = exp(sum_o q[m][o] k[n][o]).
// Writes expS as bf16 hi/lo split pairs + deterministic per-(m, n-tile)
// partial rowsums staged through smem (no atomics -> replay-deterministic).
// ---------------------------------------------------------------------------
__global__ __launch_bounds__(256, 2)
void logits_exp_bf16()
{
    extern __shared__ char smem[];
    const uint32_t sbase = smem_u32(smem);

    const int b  = blockIdx.z;
    const int mB = blockIdx.y * 128;
    const int nB = blockIdx.x * 128;
    const int tid = threadIdx.x;

    float acc[4][4][4];
#pragma unroll
    for (int mt = 0; mt < 4; mt++)
#pragma unroll
        for (int nt = 0; nt < 4; nt++)
#pragma unroll
            for (int r = 0; r < 4; r++) acc[mt][nt][r] = 0.f;

    bf16x3_mainloop_ca<C8 / 2, C8 / 2, C8 / 32>(
        g_q_hi + ((size_t)b * NN + mB) * (C8 / 2),
        g_q_lo + ((size_t)b * NN + mB) * (C8 / 2),
        g_k_hi + ((size_t)b * NN + nB) * (C8 / 2),
        g_k_lo + ((size_t)b * NN + nB) * (C8 / 2),
        sbase, acc);

    // order mainloop smem reads before reuse
    __syncthreads();

    const int lane = tid & 31, warp = tid >> 5;
    const int g = lane >> 2, tq = lane & 3;
    const int wm = (warp & 1) * 64, wn = (warp >> 1) * 32;
    const int slot = (warp >> 1) * 4 + tq;     // 0..15, unique per (ml)

    float* rps = (float*)smem;                 // [128][16]

#pragma unroll
    for (int mt = 0; mt < 4; mt++)
#pragma unroll
        for (int half = 0; half < 2; half++) {
            const int ml = wm + mt * 16 + g + half * 8;
            const size_t prow = ((size_t)b * NN + mB + ml) * (NN / 2);
            float rsum = 0.f;
#pragma unroll
            for (int nt = 0; nt < 4; nt++) {
                float e0 = __expf(acc[mt][nt][half * 2 + 0]);
                float e1 = __expf(acc[mt][nt][half * 2 + 1]);
                unsigned hi, lo;
                split2(e0, e1, hi, lo);
                const size_t pidx = prow + (nB + wn + nt * 8) / 2 + tq;
                g_P_hi[pidx] = hi;
                g_P_lo[pidx] = lo;
                rsum += e0 + e1;
            }
            rps[ml * 16 + slot] = rsum;
        }
    __syncthreads();

    if (tid < 128) {
        float s = 0.f;
#pragma unroll
        for (int i = 0; i < 16; i++) s += rps[tid * 16 + i];
        g_rs_part[((size_t)b * 32 + (nB >> 7)) * NN + mB + tid] = s;
    }
}

// ---------------------------------------------------------------------------
// Reduce partial rowsums -> per-row scale = num_styles / rowsum
// ---------------------------------------------------------------------------
__global__ __launch_bounds__(256)
void reduce_scale(const int* __restrict__ num_styles)
{
    const int idx = blockIdx.x * 256 + threadIdx.x;   // BB*NN total
    const int b = idx >> 12;
    const int m = idx & (NN - 1);
    float s = 0.f;
#pragma unroll
    for (int t = 0; t < 32; t++)
        s += g_rs_part[((size_t)b * 32 + t) * NN + m];
    g_scale[(size_t)b * NN + m] = (float)num_styles[0] / s;
}

// ---------------------------------------------------------------------------
// Heavy GEMM: out[b][c][m] = gamma*(sum_n v[c][n] expS[m][n])*scale[m]
//                           - gamma*[m==0]*corr*v[c][sidx] + x[b][c][m]
// where corr = expS[0][sidx]*scale[0] (the zeroed style entry).
// c-tiles fastest in grid.x so blocks sharing a P slice co-run (L2 reuse).
// ---------------------------------------------------------------------------
__global__ __launch_bounds__(256, 2)
void out_gemm_bf16(const float* __restrict__ x, const float* __restrict__ gamma,
                   const int* __restrict__ style_idx, float* __restrict__ out)
{
    extern __shared__ char smem[];
    const uint32_t sbase = smem_u32(smem);

    const int b  = blockIdx.z;
    const int cB = blockIdx.x * 128;
    const int mB = blockIdx.y * 128;

    float acc[4][4][4];
#pragma unroll
    for (int mt = 0; mt < 4; mt++)
#pragma unroll
        for (int nt = 0; nt < 4; nt++)
#pragma unroll
            for (int r = 0; r < 4; r++) acc[mt][nt][r] = 0.f;

    bf16x3_mainloop_ca<NN / 2, NN / 2, NN / 32>(
        g_v_hi + ((size_t)b * CC + cB) * (NN / 2),
        g_v_lo + ((size_t)b * CC + cB) * (NN / 2),
        g_P_hi + ((size_t)b * NN + mB) * (NN / 2),
        g_P_lo + ((size_t)b * NN + mB) * (NN / 2),
        sbase, acc);

    const int lane = threadIdx.x & 31, warp = threadIdx.x >> 5;
    const int g = lane >> 2, tq = lane & 3;
    const int wm = (warp & 1) * 64, wn = (warp >> 1) * 32;

    const float gm = gamma[0];

    // per-column softmax scales (8 columns per thread)
    float sc[4][2];
#pragma unroll
    for (int nt = 0; nt < 4; nt++) {
        const int m = mB + wn + nt * 8 + 2 * tq;
        sc[nt][0] = g_scale[(size_t)b * NN + m];
        sc[nt][1] = g_scale[(size_t)b * NN + m + 1];
    }

    // style-zero correction setup (only threads owning column m == 0)
    const bool fix0 = (mB == 0) && (wn == 0) && (tq == 0);
    float corr = 0.f;
    int sx = 0;
    if (fix0) {
        sx = style_idx[b];
        const float e0 = unsplit_at(g_P_hi, g_P_lo,
                                    ((size_t)b * NN + 0) * (NN / 2) + (sx >> 1),
                                    sx & 1);
        corr = e0 * g_scale[(size_t)b * NN + 0];
    }

#pragma unroll
    for (int mt = 0; mt < 4; mt++)
#pragma unroll
        for (int half = 0; half < 2; half++) {
            const int c = cB + wm + mt * 16 + g + half * 8;
            const float* xr   = x   + ((size_t)b * CC + c) * NN;
            float*       orow = out + ((size_t)b * CC + c) * NN;
#pragma unroll
            for (int nt = 0; nt < 4; nt++) {
                const int m = mB + wn + nt * 8 + 2 * tq;
                float a0 = acc[mt][nt][half * 2 + 0] * sc[nt][0];
                float a1 = acc[mt][nt][half * 2 + 1] * sc[nt][1];
                if (nt == 0 && fix0) {
                    const float vc = unsplit_at(
                        g_v_hi, g_v_lo,
                        ((size_t)b * CC + c) * (NN / 2) + (sx >> 1), sx & 1);
                    a0 -= corr * vc;           // m == 0 column
                }
                float2 r;
                r.x = gm * a0 + xr[m];
                r.y = gm * a1 + xr[m + 1];
                *(float2*)&orow[m] = r;
            }
        }
}

// ---------------------------------------------------------------------------
extern "C" void kernel_launch(void* const* d_in, const int* in_sizes, int n_in,
                              void* d_out, int out_size)
{
    const float* x     = (const float*)d_in[0];
    const float* Wq    = (const float*)d_in[1];
    const float* bq    = (const float*)d_in[2];
    const float* Wk    = (const float*)d_in[3];
    const float* bk    = (const float*)d_in[4];
    const float* Wv    = (const float*)d_in[5];
    const float* bv    = (const float*)d_in[6];
    const float* gamma = (const float*)d_in[7];
    const int*   sidx  = (const int*)d_in[8];
    const int*   nsty  = (const int*)d_in[9];
    float* out = (float*)d_out;

    cudaFuncSetAttribute(vproj_bf16,
                         cudaFuncAttributeMaxDynamicSharedMemorySize, PIPE_B);
    cudaFuncSetAttribute(logits_exp_bf16,
                         cudaFuncAttributeMaxDynamicSharedMemorySize, PIPE_B);
    cudaFuncSetAttribute(out_gemm_bf16,
                         cudaFuncAttributeMaxDynamicSharedMemorySize, PIPE_B);

    // Prep: transpose+split x, split Wv
    splitT_x<<<dim3(NN / 32, CC / 32, BB), 256>>>(x);
    split_w<<<(CC * (CC / 2)) / 256, 256>>>(Wv);

    // merged q+k projections (fp32 exact), written split [n][o]
    qkproj_kernel<<<dim3(NN / 64, 1, BB), 256>>>(Wq, bq, Wk, bk, x);

    // v projection (bf16x3, 3-stage cp.async + swizzled ldmatrix) -> split V
    vproj_bf16<<<dim3(NN / 128, CC / 128, BB), 256, PIPE_B>>>(bv);

    // logits + exp -> split expS + partial rowsums
    logits_exp_bf16<<<dim3(NN / 128, NN / 128, BB), 256, PIPE_B>>>();

    // rowsum reduce -> per-row scale
    reduce_scale<<<(BB * NN) / 256, 256>>>(nsty);

    // out = gamma * (V @ expS^T) * scale + correction + x
    out_gemm_bf16<<<dim3(CC / 128, NN / 128, BB), 256, PIPE_B>>>(x, gamma, sidx, out);
}